// round 15
// baseline (speedup 1.0000x reference)
#include <cuda_runtime.h>
#include <cuda_fp16.h>
#include <cstdint>
#include <math.h>

#define Bn      64
#define Cn      256
#define Ln      4096
#define HEADSn  8
#define Qn      16
#define Dn      32
#define NHQ     128          // HEADS*Q
#define FHn     512
#define LT1     64           // K1 tile (l per block)
#define NT1     64           // number of K1 tiles (Ln/LT1)
#define NSPLIT  2
#define LSP     2048         // L per split (Ln/NSPLIT)
#define KC      64           // K3 l-chunk (== LT1)
#define NCHUNK  (LSP/KC)     // 32
#define APITCH  72           // fp16 elems per row (144B pitch -> ldmatrix conflict-free)
#define VWP     260          // k4a vw pitch (float4 conflict-free)
#define XHP     72           // k1 x_h smem pitch (halves)
#define GP      40           // k1 G smem pitch (halves; 80B stride, conflict-free)

// ---------------- scratch (device globals: no allocs allowed) ----------------
__device__ __half  g_E  [(size_t)Bn*NHQ*Ln];               // 67 MB  exp(logit-m_t)*rstd, fp16
__device__ __half  g_x16[(size_t)Bn*Cn*Ln];                // 134 MB raw x, fp16
__device__ float4  g_part[Bn*NT1*NHQ];                     // per-tile (max, sumexp, re, -)
__device__ float2  g_ms  [Bn*NHQ];                         // (max, 1/sum)
__device__ float   g_R   [Bn*NHQ];                         // R = sum Aw*rstd*mu
__device__ float   g_Ppart[(size_t)NSPLIT*Bn*NHQ*Cn];      // 17 MB partial P_raw
__device__ float   g_A   [Bn*NHQ*Dn];                      // Aflat [B,4096]

// ---------------- fast exp (no MUFU; pure FMA/ALU) ----------------
__device__ __forceinline__ float fexp(float x) {
    float y = x * 1.4426950408889634f;
    y = fmaxf(y, -120.0f);
    float fl = floorf(y);
    float f  = y - fl;                 // [0,1)
    float p = 1.5252733e-5f;
    p = fmaf(p, f, 1.5403530e-4f);
    p = fmaf(p, f, 1.3333558e-3f);
    p = fmaf(p, f, 9.6181291e-3f);
    p = fmaf(p, f, 5.5504109e-2f);
    p = fmaf(p, f, 2.4022651e-1f);
    p = fmaf(p, f, 6.9314718e-1f);
    p = fmaf(p, f, 1.0f);
    int i = (int)fl;
    return p * __int_as_float((i + 127) << 23);
}

// mma.sync m16n8k16 fp16 (row.col), fp32 accumulate — base-arch tensor path
__device__ __forceinline__ void mma16816(float* d, const uint32_t* a, const uint32_t* b) {
    asm volatile("mma.sync.aligned.m16n8k16.row.col.f32.f16.f16.f32 "
        "{%0,%1,%2,%3}, {%4,%5,%6,%7}, {%8,%9}, {%0,%1,%2,%3};"
        : "+f"(d[0]), "+f"(d[1]), "+f"(d[2]), "+f"(d[3])
        : "r"(a[0]), "r"(a[1]), "r"(a[2]), "r"(a[3]), "r"(b[0]), "r"(b[1]));
}

__device__ __forceinline__ void ldm_x4(uint32_t* r, uint32_t addr) {
    asm volatile("ldmatrix.sync.aligned.m8n8.x4.shared.b16 {%0,%1,%2,%3}, [%4];"
        : "=r"(r[0]), "=r"(r[1]), "=r"(r[2]), "=r"(r[3]) : "r"(addr));
}
__device__ __forceinline__ void ldm_x4_trans(uint32_t* r, uint32_t addr) {
    asm volatile("ldmatrix.sync.aligned.m8n8.x4.trans.shared.b16 {%0,%1,%2,%3}, [%4];"
        : "=r"(r[0]), "=r"(r[1]), "=r"(r[2]), "=r"(r[3]) : "r"(addr));
}

#define CP_ASYNC16(dst, src) \
    asm volatile("cp.async.ca.shared.global [%0], [%1], 16;" :: "r"(dst), "l"(src) : "memory")
#define CP_COMMIT()  asm volatile("cp.async.commit_group;" ::: "memory")
#define CP_WAIT1()   asm volatile("cp.async.wait_group 1;" ::: "memory")
#define CP_WAIT0()   asm volatile("cp.async.wait_group 0;" ::: "memory")

// ---------------- no-op (launch-order shim so ncu's capture lands on k1) ----------------
__global__ void knop() {}

// ---------------- K1: LN stats + tensor-core logits + softmax + E'(rstd-folded) + x16 ----------------
#define XH_BYTES (Cn*XHP*2)                 // 36864
#define RED_OFF  (XH_BYTES)
#define K1_DYN   (XH_BYTES + 512*16*2)      // 53248

__global__ __launch_bounds__(512, 2) void k1(const float* __restrict__ x,
                                             const float* __restrict__ gamma,
                                             const float* __restrict__ beta,
                                             const float* __restrict__ attw)
{
    extern __shared__ char sm1[];
    __half* x_h  = (__half*)sm1;                  // [256][XHP] halves (raw x fp16)
    float4* redS = (float4*)(sm1 + RED_OFF);      // [512]
    float4* redQ = redS + 512;                    // [512]

    __shared__ __half G_s[NHQ*GP];                // G = w*gamma, [hq][GP]
    __shared__ float  S_s[NHQ], T_s[NHQ];
    __shared__ float2 stats_s[LT1];               // (mu, rstd)
    __shared__ float  gms[Cn], bts[Cn];
    __shared__ float4 redms[HEADSn][2][Qn];       // cross-warp (m, s, re) exchange

    const int b = blockIdx.y, tile = blockIdx.x;
    const int tid  = threadIdx.x;
    const int lgrp = tid & 15;
    const int l4   = tile*LT1 + lgrp*4;

    for (int i = tid; i < Cn; i += 512) { gms[i] = gamma[i]; bts[i] = beta[i]; }
    __syncthreads();

    // ---- phase 0: G (fp16), S, T per hq ----
    if (tid < NHQ) {
        const int h = tid >> 4;
        const float* wp = attw + tid*Dn;
        float S = 0.f, T = 0.f;
        __half2* grow = (__half2*)&G_s[tid*GP];
        #pragma unroll
        for (int c2 = 0; c2 < 16; c2++) {
            float w0 = wp[2*c2], w1 = wp[2*c2+1];
            float G0 = w0 * gms[h*Dn + 2*c2];
            float G1 = w1 * gms[h*Dn + 2*c2 + 1];
            S += G0 + G1;
            T += w0*bts[h*Dn + 2*c2] + w1*bts[h*Dn + 2*c2 + 1];
            grow[c2] = __floats2half2_rn(G0, G1);
        }
        S_s[tid] = S; T_s[tid] = T;
    }

    const float* xb = x + (size_t)b*Cn*Ln;

    // ---- phase A: stats; stage raw x fp16 into SMEM AND to g_x16 ----
    {
        const int cg = tid >> 4;                  // 32 groups of 8 channels
        __half* x16b = g_x16 + (size_t)b*Cn*Ln;
        float4 s4 = make_float4(0.f,0.f,0.f,0.f);
        float4 q4 = make_float4(0.f,0.f,0.f,0.f);
        #pragma unroll
        for (int cc = 0; cc < 8; cc++) {
            const int c = cg*8 + cc;
            float4 v = *(const float4*)&xb[(size_t)c*Ln + l4];
            s4.x += v.x; s4.y += v.y; s4.z += v.z; s4.w += v.w;
            q4.x = fmaf(v.x, v.x, q4.x); q4.y = fmaf(v.y, v.y, q4.y);
            q4.z = fmaf(v.z, v.z, q4.z); q4.w = fmaf(v.w, v.w, q4.w);
            __half2 a01 = __floats2half2_rn(v.x, v.y);
            __half2 a23 = __floats2half2_rn(v.z, v.w);
            uint2 pk = make_uint2(*reinterpret_cast<uint32_t*>(&a01),
                                  *reinterpret_cast<uint32_t*>(&a23));
            *(uint2*)&x_h[c*XHP + lgrp*4] = pk;
            *(uint2*)&x16b[(size_t)c*Ln + l4] = pk;
        }
        redS[tid] = s4; redQ[tid] = q4;
        __syncthreads();
        if (tid < LT1) {
            const int lg = tid >> 2, li = tid & 3;
            float s = 0.f, q = 0.f;
            #pragma unroll
            for (int cg2 = 0; cg2 < 32; cg2++) {
                s += ((const float*)&redS[cg2*16 + lg])[li];
                q += ((const float*)&redQ[cg2*16 + lg])[li];
            }
            float mu  = s * (1.f/Cn);
            float var = q * (1.f/Cn) - mu*mu;
            stats_s[tid] = make_float2(mu, rsqrtf(var + 1e-6f));
        }
        __syncthreads();
    }

    // ---- phase C: logits via mma.sync; softmax; E' store (rstd folded, coalesced) ----
    {
        const int w    = tid >> 5, lane = tid & 31;
        const int h    = w >> 1, lh = w & 1;       // head, l-half (32 l)
        const int g    = lane >> 3, r = lane & 7;

        const uint32_t smbG = (uint32_t)__cvta_generic_to_shared(G_s);
        const uint32_t smbX = (uint32_t)__cvta_generic_to_shared(x_h);

        uint32_t a[2][4];
        #pragma unroll
        for (int k = 0; k < 2; k++)
            ldm_x4(a[k], smbG + 2u*(uint32_t)((h*16 + ((g & 1) << 3) + r)*GP + k*16 + ((g >> 1) << 3)));

        float acc[4][4];
        #pragma unroll
        for (int j = 0; j < 4; j++)
            #pragma unroll
            for (int e = 0; e < 4; e++) acc[j][e] = 0.f;

        #pragma unroll
        for (int k = 0; k < 2; k++) {
            #pragma unroll
            for (int lp = 0; lp < 2; lp++) {
                uint32_t bb[4];
                ldm_x4_trans(bb, smbX + 2u*(uint32_t)((h*Dn + k*16 + (lane & 15))*XHP
                                                      + lh*32 + lp*16 + ((lane >> 4) << 3)));
                mma16816(acc[lp*2+0], a[k], bb);
                mma16816(acc[lp*2+1], a[k], bb + 2);
            }
        }

        const int r1  = lane >> 2;
        const int c2  = (lane & 3)*2;
        const int hq1 = h*Qn + r1, hq2 = hq1 + 8;
        const float S1 = S_s[hq1], T1 = T_s[hq1];
        const float S2 = S_s[hq2], T2 = T_s[hq2];
        #pragma unroll
        for (int j = 0; j < 4; j++) {
            #pragma unroll
            for (int e = 0; e < 2; e++) {
                float2 st = stats_s[lh*32 + j*8 + c2 + e];
                float base = st.y * st.x;
                acc[j][e]   = fmaf(acc[j][e],   st.y, fmaf(-base, S1, T1));
                acc[j][2+e] = fmaf(acc[j][2+e], st.y, fmaf(-base, S2, T2));
            }
        }

        float m1 = -1e30f, m2 = -1e30f;
        #pragma unroll
        for (int j = 0; j < 4; j++) {
            m1 = fmaxf(m1, fmaxf(acc[j][0], acc[j][1]));
            m2 = fmaxf(m2, fmaxf(acc[j][2], acc[j][3]));
        }
        m1 = fmaxf(m1, __shfl_xor_sync(0xFFFFFFFFu, m1, 1));
        m1 = fmaxf(m1, __shfl_xor_sync(0xFFFFFFFFu, m1, 2));
        m2 = fmaxf(m2, __shfl_xor_sync(0xFFFFFFFFu, m2, 1));
        m2 = fmaxf(m2, __shfl_xor_sync(0xFFFFFFFFu, m2, 2));

        float s1 = 0.f, s2 = 0.f;
        #pragma unroll
        for (int j = 0; j < 4; j++) {
            acc[j][0] = fexp(acc[j][0] - m1);
            acc[j][1] = fexp(acc[j][1] - m1);
            acc[j][2] = fexp(acc[j][2] - m2);
            acc[j][3] = fexp(acc[j][3] - m2);
            s1 += acc[j][0] + acc[j][1];
            s2 += acc[j][2] + acc[j][3];
        }
        s1 += __shfl_xor_sync(0xFFFFFFFFu, s1, 1);
        s1 += __shfl_xor_sync(0xFFFFFFFFu, s1, 2);
        s2 += __shfl_xor_sync(0xFFFFFFFFu, s2, 1);
        s2 += __shfl_xor_sync(0xFFFFFFFFu, s2, 2);

        // fold rstd into E (acc -> E' pre-f) and accumulate re = sum E'*mu
        float re1 = 0.f, re2 = 0.f;
        #pragma unroll
        for (int j = 0; j < 4; j++) {
            #pragma unroll
            for (int e = 0; e < 2; e++) {
                float2 st = stats_s[lh*32 + j*8 + c2 + e];
                acc[j][e]   *= st.y;
                acc[j][2+e] *= st.y;
                re1 = fmaf(acc[j][e],   st.x, re1);
                re2 = fmaf(acc[j][2+e], st.x, re2);
            }
        }
        re1 += __shfl_xor_sync(0xFFFFFFFFu, re1, 1);
        re1 += __shfl_xor_sync(0xFFFFFFFFu, re1, 2);
        re2 += __shfl_xor_sync(0xFFFFFFFFu, re2, 1);
        re2 += __shfl_xor_sync(0xFFFFFFFFu, re2, 2);

        if ((lane & 3) == 0) {
            redms[h][lh][r1]     = make_float4(m1, s1, re1, 0.f);
            redms[h][lh][r1 + 8] = make_float4(m2, s2, re2, 0.f);
        }
        __syncthreads();

        float4 o1 = redms[h][1 - lh][r1];
        float4 o2 = redms[h][1 - lh][r1 + 8];
        float mt1 = fmaxf(m1, o1.x), mt2 = fmaxf(m2, o2.x);
        float f1  = fexp(m1 - mt1),  f2  = fexp(m2 - mt2);
        if (lh == 0 && (lane & 3) == 0) {
            float fo1 = fexp(o1.x - mt1), fo2 = fexp(o2.x - mt2);
            g_part[(b*NT1 + tile)*NHQ + hq1] =
                make_float4(mt1, s1*f1 + o1.y*fo1, re1*f1 + o1.z*fo1, 0.f);
            g_part[(b*NT1 + tile)*NHQ + hq2] =
                make_float4(mt2, s2*f2 + o2.y*fo2, re2*f2 + o2.z*fo2, 0.f);
        }

        // E' stores: quad 4x4 transpose -> one uint4 (16B) per lane per row
        uint32_t a1v[4], a2v[4];
        #pragma unroll
        for (int j = 0; j < 4; j++) {
            __half2 v1 = __floats2half2_rn(acc[j][0]*f1, acc[j][1]*f1);
            __half2 v2 = __floats2half2_rn(acc[j][2]*f2, acc[j][3]*f2);
            a1v[j] = *reinterpret_cast<uint32_t*>(&v1);
            a2v[j] = *reinterpret_cast<uint32_t*>(&v2);
        }
        const int lq = lane & 3;
        uint32_t b1[4], b2[4];
        b1[lq] = a1v[lq]; b2[lq] = a2v[lq];
        #pragma unroll
        for (int s = 1; s < 4; s++) {
            int jdst = (lq + s) & 3;
            int jsrc = (lq - s) & 3;
            int srcl = (lane & ~3) | jdst;
            b1[jdst] = __shfl_sync(0xFFFFFFFFu, a1v[jsrc], srcl);
            b2[jdst] = __shfl_sync(0xFFFFFFFFu, a2v[jsrc], srcl);
        }
        __half* e1 = g_E + (size_t)(b*NHQ + hq1)*Ln + tile*LT1 + lh*32 + lq*8;
        __half* e2 = g_E + (size_t)(b*NHQ + hq2)*Ln + tile*LT1 + lh*32 + lq*8;
        *(uint4*)e1 = make_uint4(b1[0], b1[1], b1[2], b1[3]);
        *(uint4*)e2 = make_uint4(b2[0], b2[1], b2[2], b2[3]);
    }
}

// ---------------- K2: merge softmax partials -> g_ms, g_R ----------------
__global__ void k2()
{
    const int idx = blockIdx.x*256 + threadIdx.x;
    if (idx >= Bn*NHQ) return;
    const int b = idx >> 7, hq = idx & 127;
    const float4* gp = g_part + b*NT1*NHQ + hq;
    float m = -1e30f;
    for (int t = 0; t < NT1; t++) m = fmaxf(m, gp[t*NHQ].x);
    float s = 0.f, r = 0.f;
    for (int t = 0; t < NT1; t++) {
        float4 p = gp[t*NHQ];
        float e = fexp(p.x - m);
        s += p.y * e;
        r += p.z * e;
    }
    float inv = 1.f/s;
    g_ms[idx] = make_float2(m, inv);
    g_R[idx]  = r * inv;
}

// ---------------- K3: P_raw = A' @ x16^T, fp16 GEMM, 3-stage ring (1 barrier/chunk) ----------------
#define A_OFF  0
#define B_OFF  (128*APITCH)
#define TILE_HALVES (128*APITCH + 256*APITCH)   // 27648
#define TILE_BYTES  (TILE_HALVES*2)             // 55296
#define K3_DYN (3*TILE_BYTES)                   // 165888

__global__ __launch_bounds__(512, 1) void k3()
{
    extern __shared__ __half sm3[];
    __shared__ float2 ms_s[NHQ];

    const int split = blockIdx.x, b = blockIdx.y;
    const int tid  = threadIdx.x;
    const int wid  = tid >> 5, lane = tid & 31;
    const int mw   = wid >> 2, nw = wid & 3;

    for (int i = tid; i < NHQ; i += 512) ms_s[i] = g_ms[b*NHQ + i];

    const int hqA = tid >> 2, l0A = (tid & 3) * 16;   // A: 128 rows x 64
    const int cB  = tid >> 1, l0B = (tid & 1) * 32;   // B: 256 rows x 64
    __syncthreads();
    const float m_g = ms_s[hqA].x, inv_s = ms_s[hqA].y;

    const __half*  eA = g_E   + (size_t)(b*NHQ + hqA)*Ln + split*LSP + l0A;
    const __half*  xB = g_x16 + ((size_t)b*Cn + cB)*Ln   + split*LSP + l0B;
    const float4*  gp = g_part + (b*NT1 + split*(NT1/NSPLIT))*NHQ + hqA;

    const uint32_t smb = (uint32_t)__cvta_generic_to_shared(sm3);
    const uint32_t dstB = smb + 2u*(uint32_t)(B_OFF + cB*APITCH + l0B);

    const int g = lane >> 3, r = lane & 7;
    const uint32_t addrA0 = smb + 2u*((uint32_t)((mw*32 + ((g & 1) << 3) + r)*APITCH + ((g >> 1) << 3)));
    const uint32_t addrB0 = smb + 2u*((uint32_t)(B_OFF + (nw*64 + ((g >> 1) << 3) + r)*APITCH + ((g & 1) << 3)));

    float acc[2][8][4];
    #pragma unroll
    for (int i = 0; i < 2; i++)
        #pragma unroll
        for (int j = 0; j < 8; j++)
            #pragma unroll
            for (int e = 0; e < 4; e++) acc[i][j][e] = 0.f;

    auto storeA = [&](uint32_t half_off, const uint4* ar, float f) {
        #pragma unroll
        for (int u = 0; u < 2; u++) {
            uint32_t w[4] = {ar[u].x, ar[u].y, ar[u].z, ar[u].w};
            uint32_t o[4];
            #pragma unroll
            for (int j = 0; j < 4; j++) {
                __half2 h = *reinterpret_cast<__half2*>(&w[j]);
                float2 v = __half22float2(h);
                __half2 rr = __floats2half2_rn(v.x * f, v.y * f);
                o[j] = *reinterpret_cast<uint32_t*>(&rr);
            }
            *(uint4*)(sm3 + half_off + A_OFF + hqA*APITCH + l0A + u*8) =
                make_uint4(o[0], o[1], o[2], o[3]);
        }
    };

    // ---- prologue ----
    {
        CP_ASYNC16(dstB +  0, xB);
        CP_ASYNC16(dstB + 16, xB + 8);
        CP_ASYNC16(dstB + 32, xB + 16);
        CP_ASYNC16(dstB + 48, xB + 24);
        CP_COMMIT();
    }
    uint4 aregs[2];
    aregs[0] = *(const uint4*)(eA);
    aregs[1] = *(const uint4*)(eA + 8);
    storeA(0, aregs, fexp(gp[0].x - m_g) * inv_s);
    aregs[0] = *(const uint4*)(eA + KC);
    aregs[1] = *(const uint4*)(eA + KC + 8);
    float fcur = fexp(gp[NHQ].x - m_g) * inv_s;

    for (int t = 0; t < NCHUNK; t++) {
        const uint32_t bufo = (uint32_t)((t % 3) * TILE_BYTES);

        if (t + 1 < NCHUNK) {
            const uint32_t nb = (uint32_t)(((t + 1) % 3) * TILE_BYTES);
            const __half* src = xB + (t + 1)*KC;
            CP_ASYNC16(nb + dstB +  0, src);
            CP_ASYNC16(nb + dstB + 16, src + 8);
            CP_ASYNC16(nb + dstB + 32, src + 16);
            CP_ASYNC16(nb + dstB + 48, src + 24);
            CP_COMMIT();
            storeA(nb >> 1, aregs, fcur);
            if (t + 2 < NCHUNK) {
                const __half* ea = eA + (t + 2)*KC;
                aregs[0] = *(const uint4*)(ea);
                aregs[1] = *(const uint4*)(ea + 8);
                fcur = fexp(gp[(t + 2)*NHQ].x - m_g) * inv_s;
            }
            CP_WAIT1();
        } else {
            CP_WAIT0();
        }
        __syncthreads();

        #pragma unroll
        for (int ks = 0; ks < 4; ks++) {
            uint32_t a0[4], a1[4];
            ldm_x4(a0, bufo + addrA0 + 2u*(uint32_t)(16*ks));
            ldm_x4(a1, bufo + addrA0 + 2u*(uint32_t)(16*APITCH + 16*ks));
            #pragma unroll
            for (int jj = 0; jj < 4; jj++) {
                uint32_t bfr[4];
                ldm_x4(bfr, bufo + addrB0 + 2u*(uint32_t)(16*jj*APITCH + 16*ks));
                mma16816(acc[0][2*jj],   a0, bfr);
                mma16816(acc[0][2*jj+1], a0, bfr + 2);
                mma16816(acc[1][2*jj],   a1, bfr);
                mma16816(acc[1][2*jj+1], a1, bfr + 2);
            }
        }
    }

    float* pp = g_Ppart + (((size_t)split*Bn + b)*NHQ)*Cn;
    #pragma unroll
    for (int i = 0; i < 2; i++) {
        const int row = mw*32 + i*16 + (lane >> 2);
        #pragma unroll
        for (int j = 0; j < 8; j++) {
            const int col = nw*64 + j*8 + (lane & 3)*2;
            *(float2*)(pp + (size_t)row*Cn + col)     = make_float2(acc[i][j][0], acc[i][j][1]);
            *(float2*)(pp + (size_t)(row+8)*Cn + col) = make_float2(acc[i][j][2], acc[i][j][3]);
        }
    }
}

// ---------------- K4a: P = gamma*(Praw - R) + beta fold + A = P @ val_w^T + val_b ----------------
__global__ void k4a(const float* __restrict__ val_w, const float* __restrict__ val_b,
                    const float* __restrict__ gamma, const float* __restrict__ beta)
{
    extern __shared__ float sm[];
    float* vw = sm;              // [32][VWP]  val_w * gamma
    float* ps = sm + 32*VWP;     // [16][256]  P_raw summed
    __shared__ float gmm[Cn], btt[Cn];
    __shared__ float VS[32], VB[32];
    __shared__ float Rsh[Qn];
    const int h = blockIdx.x, b = blockIdx.y;
    const int tid = threadIdx.x;

    for (int i = tid; i < Cn; i += 256) { gmm[i] = gamma[i]; btt[i] = beta[i]; }
    if (tid < 32) { VS[tid] = 0.f; VB[tid] = 0.f; }
    if (tid < Qn) Rsh[tid] = g_R[b*NHQ + h*Qn + tid];
    __syncthreads();

    for (int i = tid*4; i < 32*Cn; i += 256*4) {
        int r = i >> 8, c = i & 255;
        float4 v = *(const float4*)&val_w[(size_t)(h*32 + r)*Cn + c];
        float4 g = *(const float4*)&gmm[c];
        float4 bt4 = *(const float4*)&btt[c];
        float4 vg = make_float4(v.x*g.x, v.y*g.y, v.z*g.z, v.w*g.w);
        *(float4*)&vw[r*VWP + c] = vg;
        atomicAdd(&VS[r], vg.x + vg.y + vg.z + vg.w);
        atomicAdd(&VB[r], v.x*bt4.x + v.y*bt4.y + v.z*bt4.z + v.w*bt4.w);
    }
    for (int i = tid*4; i < Qn*Cn; i += 256*4) {
        int q = i >> 8, c = i & 255;
        int hq = h*Qn + q;
        float4 s0 = *(const float4*)&g_Ppart[(((size_t)0*Bn + b)*NHQ + hq)*Cn + c];
        float4 s1 = *(const float4*)&g_Ppart[(((size_t)1*Bn + b)*NHQ + hq)*Cn + c];
        *(float4*)&ps[i] = make_float4(s0.x + s1.x, s0.y + s1.y, s0.z + s1.z, s0.w + s1.w);
    }
    __syncthreads();

    for (int o = tid; o < Qn*32; o += 256) {
        int q = o >> 5, d = o & 31;
        float a = val_b[h*32 + d] + VB[d] - Rsh[q]*VS[d];
        #pragma unroll 8
        for (int c = 0; c < Cn; c += 4) {
            float4 pv = *(const float4*)&ps[q*Cn + c];
            float4 wv = *(const float4*)&vw[d*VWP + c];
            a = fmaf(pv.x, wv.x, a);
            a = fmaf(pv.y, wv.y, a);
            a = fmaf(pv.z, wv.z, a);
            a = fmaf(pv.w, wv.w, a);
        }
        g_A[b*4096 + (h*Qn + q)*32 + d] = a;
    }
}

// ---------------- K4b: out = A @ fin_w^T + fin_b ----------------
__global__ void kinit(float* __restrict__ out, const float* __restrict__ fin_b)
{
    out[blockIdx.x*FHn + threadIdx.x] = fin_b[threadIdx.x];
}

__global__ void k4b(const float* __restrict__ fin_w, float* __restrict__ out)
{
    __shared__ float At[64*65];
    __shared__ float Wt[32*65];
    const int ft = blockIdx.x;
    const int js = blockIdx.y;
    const int tid = threadIdx.x;
    const int ty = tid >> 5, tx = tid & 31;
    const int f0 = ft*32;

    float acc[8];
    #pragma unroll
    for (int i = 0; i < 8; i++) acc[i] = 0.f;

    for (int sub = 0; sub < 8; sub++) {
        const int j0 = js*512 + sub*64;
        __syncthreads();
        for (int i = tid; i < 64*64; i += 256) {
            int bb = i >> 6, jj = i & 63;
            At[bb*65 + jj] = g_A[bb*4096 + j0 + jj];
        }
        for (int i = tid; i < 32*64; i += 256) {
            int r = i >> 6, jj = i & 63;
            Wt[r*65 + jj] = fin_w[(size_t)(f0 + r)*4096 + j0 + jj];
        }
        __syncthreads();
        #pragma unroll 8
        for (int j = 0; j < 64; j++) {
            float w = Wt[tx*65 + j];
            #pragma unroll
            for (int i = 0; i < 8; i++)
                acc[i] = fmaf(At[(ty*8 + i)*65 + j], w, acc[i]);
        }
    }
    #pragma unroll
    for (int i = 0; i < 8; i++)
        atomicAdd(&out[(ty*8 + i)*FHn + f0 + tx], acc[i]);
}

// ---------------- launch ----------------
extern "C" void kernel_launch(void* const* d_in, const int* in_sizes, int n_in,
                              void* d_out, int out_size)
{
    const float* x    = (const float*)d_in[0];
    const float* gam  = (const float*)d_in[1];
    const float* bet  = (const float*)d_in[2];
    const float* attw = (const float*)d_in[3];
    const float* valw = (const float*)d_in[4];
    const float* valb = (const float*)d_in[5];
    const float* finw = (const float*)d_in[6];
    const float* finb = (const float*)d_in[7];
    float* out = (float*)d_out;

    const int smem_k4a = (32*VWP + 16*Cn)*4;

    cudaFuncSetAttribute(k1,  cudaFuncAttributeMaxDynamicSharedMemorySize, K1_DYN);
    cudaFuncSetAttribute(k3,  cudaFuncAttributeMaxDynamicSharedMemorySize, K3_DYN);
    cudaFuncSetAttribute(k4a, cudaFuncAttributeMaxDynamicSharedMemorySize, smem_k4a);

    // shims so k1 (changed, dominant) is the 4th launch for the ncu capture
    knop<<<1, 32>>>();
    knop<<<1, 32>>>();
    kinit<<<Bn, FHn>>>(out, finb);
    k1  <<<dim3(NT1, Bn),    512, K1_DYN >>>(x, gam, bet, attw);
    k2  <<<32, 256>>>();
    k3  <<<dim3(NSPLIT, Bn), 512, K3_DYN >>>();
    k4a <<<dim3(HEADSn, Bn), 256, smem_k4a>>>(valw, valb, gam, bet);
    k4b <<<dim3(16, 8), 256>>>(finw, out);
}

// round 16
// speedup vs baseline: 1.2256x; 1.2256x over previous
#include <cuda_runtime.h>
#include <cuda_fp16.h>
#include <cstdint>
#include <math.h>

#define Bn      64
#define Cn      256
#define Ln      4096
#define HEADSn  8
#define Qn      16
#define Dn      32
#define NHQ     128          // HEADS*Q
#define FHn     512
#define LT1     64           // K1 tile (l per block)
#define NT1     64           // number of K1 tiles (Ln/LT1)
#define NSPLIT  2
#define LSP     2048         // L per split (Ln/NSPLIT)
#define KC      64           // K3 l-chunk (== LT1)
#define NCHUNK  (LSP/KC)     // 32
#define APITCH  72           // fp16 elems per row (144B pitch -> ldmatrix conflict-free)
#define VWP     260          // k4a vw pitch (float4 conflict-free)
#define XHP     72           // k1 x_h smem pitch (halves)
#define GP      40           // k1 G smem pitch (halves; 80B stride, conflict-free)

// ---------------- scratch (device globals: no allocs allowed) ----------------
__device__ __half  g_E  [(size_t)Bn*NHQ*Ln];               // 67 MB  exp(logit - m_tile), fp16
__device__ __half  g_xn [(size_t)Bn*Cn*Ln];                // 134 MB LayerNormed x, fp16
__device__ float2  g_part[Bn*NT1*NHQ];                     // per-tile (max, sumexp)
__device__ float2  g_ms  [Bn*NHQ];                         // (max, 1/sum)
__device__ float   g_Ppart[(size_t)NSPLIT*Bn*NHQ*Cn];      // 17 MB partial P
__device__ float   g_A   [Bn*NHQ*Dn];                      // Aflat [B,4096]

// ---------------- fast exp (no MUFU; pure FMA/ALU) ----------------
__device__ __forceinline__ float fexp(float x) {
    float y = x * 1.4426950408889634f;
    y = fmaxf(y, -120.0f);
    float fl = floorf(y);
    float f  = y - fl;                 // [0,1)
    float p = 1.5252733e-5f;
    p = fmaf(p, f, 1.5403530e-4f);
    p = fmaf(p, f, 1.3333558e-3f);
    p = fmaf(p, f, 9.6181291e-3f);
    p = fmaf(p, f, 5.5504109e-2f);
    p = fmaf(p, f, 2.4022651e-1f);
    p = fmaf(p, f, 6.9314718e-1f);
    p = fmaf(p, f, 1.0f);
    int i = (int)fl;
    return p * __int_as_float((i + 127) << 23);
}

// mma.sync m16n8k16 fp16 (row.col), fp32 accumulate — base-arch tensor path
__device__ __forceinline__ void mma16816(float* d, const uint32_t* a, const uint32_t* b) {
    asm volatile("mma.sync.aligned.m16n8k16.row.col.f32.f16.f16.f32 "
        "{%0,%1,%2,%3}, {%4,%5,%6,%7}, {%8,%9}, {%0,%1,%2,%3};"
        : "+f"(d[0]), "+f"(d[1]), "+f"(d[2]), "+f"(d[3])
        : "r"(a[0]), "r"(a[1]), "r"(a[2]), "r"(a[3]), "r"(b[0]), "r"(b[1]));
}

__device__ __forceinline__ void ldm_x4(uint32_t* r, uint32_t addr) {
    asm volatile("ldmatrix.sync.aligned.m8n8.x4.shared.b16 {%0,%1,%2,%3}, [%4];"
        : "=r"(r[0]), "=r"(r[1]), "=r"(r[2]), "=r"(r[3]) : "r"(addr));
}
__device__ __forceinline__ void ldm_x4_trans(uint32_t* r, uint32_t addr) {
    asm volatile("ldmatrix.sync.aligned.m8n8.x4.trans.shared.b16 {%0,%1,%2,%3}, [%4];"
        : "=r"(r[0]), "=r"(r[1]), "=r"(r[2]), "=r"(r[3]) : "r"(addr));
}

#define CP_ASYNC16(dst, src) \
    asm volatile("cp.async.ca.shared.global [%0], [%1], 16;" :: "r"(dst), "l"(src) : "memory")
#define CP_COMMIT()  asm volatile("cp.async.commit_group;" ::: "memory")
#define CP_WAIT1()   asm volatile("cp.async.wait_group 1;" ::: "memory")
#define CP_WAIT0()   asm volatile("cp.async.wait_group 0;" ::: "memory")

// ---------------- K1: LN stats + tensor-core logits + softmax partials + E/xn ----------------
#define XH_BYTES (Cn*XHP*2)                 // 36864
#define RED_OFF  (XH_BYTES)
#define K1_DYN   (XH_BYTES + 512*16*2)      // 53248

__global__ __launch_bounds__(512, 2) void k1(const float* __restrict__ x,
                                             const float* __restrict__ gamma,
                                             const float* __restrict__ beta,
                                             const float* __restrict__ attw)
{
    extern __shared__ char sm1[];
    __half* x_h  = (__half*)sm1;                  // [256][XHP] halves (raw x fp16)
    float4* redS = (float4*)(sm1 + RED_OFF);      // [512]
    float4* redQ = redS + 512;                    // [512]

    __shared__ __half G_s[NHQ*GP];                // G = w*gamma, [hq][GP]
    __shared__ float  S_s[NHQ], T_s[NHQ];
    __shared__ float2 stats_s[LT1];               // (mu, rstd)
    __shared__ float  gms[Cn], bts[Cn];
    __shared__ float2 redms[HEADSn][2][Qn];       // cross-warp (m,s) exchange

    const int b = blockIdx.y, tile = blockIdx.x;
    const int tid  = threadIdx.x;
    const int lgrp = tid & 15;
    const int l4   = tile*LT1 + lgrp*4;

    for (int i = tid; i < Cn; i += 512) { gms[i] = gamma[i]; bts[i] = beta[i]; }
    __syncthreads();

    // ---- phase 0: G (fp16), S, T per hq ----
    if (tid < NHQ) {
        const int h = tid >> 4;
        const float* wp = attw + tid*Dn;
        float S = 0.f, T = 0.f;
        __half2* grow = (__half2*)&G_s[tid*GP];
        #pragma unroll
        for (int c2 = 0; c2 < 16; c2++) {
            float w0 = wp[2*c2], w1 = wp[2*c2+1];
            float G0 = w0 * gms[h*Dn + 2*c2];
            float G1 = w1 * gms[h*Dn + 2*c2 + 1];
            S += G0 + G1;
            T += w0*bts[h*Dn + 2*c2] + w1*bts[h*Dn + 2*c2 + 1];
            grow[c2] = __floats2half2_rn(G0, G1);
        }
        S_s[tid] = S; T_s[tid] = T;
    }

    const float* xb = x + (size_t)b*Cn*Ln;

    // ---- phase A: stats from fp32 x; stage raw x as fp16 into SMEM ----
    {
        const int cg = tid >> 4;                  // 32 groups of 8 channels
        float4 s4 = make_float4(0.f,0.f,0.f,0.f);
        float4 q4 = make_float4(0.f,0.f,0.f,0.f);
        #pragma unroll
        for (int cc = 0; cc < 8; cc++) {
            const int c = cg*8 + cc;
            float4 v = *(const float4*)&xb[(size_t)c*Ln + l4];
            s4.x += v.x; s4.y += v.y; s4.z += v.z; s4.w += v.w;
            q4.x = fmaf(v.x, v.x, q4.x); q4.y = fmaf(v.y, v.y, q4.y);
            q4.z = fmaf(v.z, v.z, q4.z); q4.w = fmaf(v.w, v.w, q4.w);
            __half2 a01 = __floats2half2_rn(v.x, v.y);
            __half2 a23 = __floats2half2_rn(v.z, v.w);
            *(uint2*)&x_h[c*XHP + lgrp*4] =
                make_uint2(*reinterpret_cast<uint32_t*>(&a01),
                           *reinterpret_cast<uint32_t*>(&a23));
        }
        redS[tid] = s4; redQ[tid] = q4;
        __syncthreads();
        if (tid < LT1) {
            const int lg = tid >> 2, li = tid & 3;
            float s = 0.f, q = 0.f;
            #pragma unroll
            for (int cg2 = 0; cg2 < 32; cg2++) {
                s += ((const float*)&redS[cg2*16 + lg])[li];
                q += ((const float*)&redQ[cg2*16 + lg])[li];
            }
            float mu  = s * (1.f/Cn);
            float var = q * (1.f/Cn) - mu*mu;
            stats_s[tid] = make_float2(mu, rsqrtf(var + 1e-6f));
        }
        __syncthreads();
    }

    // ---- phase B: xn = LN(x) from x_h -> g_xn ----
    {
        const int cg = tid >> 4;
        float2 st0 = stats_s[lgrp*4+0], st1 = stats_s[lgrp*4+1];
        float2 st2 = stats_s[lgrp*4+2], st3 = stats_s[lgrp*4+3];
        __half* xnb = g_xn + (size_t)b*Cn*Ln;
        #pragma unroll
        for (int cc = 0; cc < 8; cc++) {
            const int c = cg*8 + cc;
            uint2 u = *(const uint2*)&x_h[c*XHP + lgrp*4];
            float2 f01 = __half22float2(*reinterpret_cast<__half2*>(&u.x));
            float2 f23 = __half22float2(*reinterpret_cast<__half2*>(&u.y));
            const float gg = gms[c], bb = bts[c];
            __half2 o01 = __floats2half2_rn((f01.x - st0.x)*st0.y*gg + bb,
                                            (f01.y - st1.x)*st1.y*gg + bb);
            __half2 o23 = __floats2half2_rn((f23.x - st2.x)*st2.y*gg + bb,
                                            (f23.y - st3.x)*st3.y*gg + bb);
            *(uint2*)&xnb[(size_t)c*Ln + l4] =
                make_uint2(*reinterpret_cast<uint32_t*>(&o01),
                           *reinterpret_cast<uint32_t*>(&o23));
        }
    }

    // ---- phase C: logits via mma.sync; softmax; E store ----
    {
        const int w    = tid >> 5, lane = tid & 31;
        const int h    = w >> 1, lh = w & 1;       // head, l-half (32 l)
        const int g    = lane >> 3, r = lane & 7;

        const uint32_t smbG = (uint32_t)__cvta_generic_to_shared(G_s);
        const uint32_t smbX = (uint32_t)__cvta_generic_to_shared(x_h);

        uint32_t a[2][4];
        #pragma unroll
        for (int k = 0; k < 2; k++)
            ldm_x4(a[k], smbG + 2u*(uint32_t)((h*16 + ((g & 1) << 3) + r)*GP + k*16 + ((g >> 1) << 3)));

        float acc[4][4];
        #pragma unroll
        for (int j = 0; j < 4; j++)
            #pragma unroll
            for (int e = 0; e < 4; e++) acc[j][e] = 0.f;

        #pragma unroll
        for (int k = 0; k < 2; k++) {
            #pragma unroll
            for (int lp = 0; lp < 2; lp++) {
                uint32_t bb[4];
                ldm_x4_trans(bb, smbX + 2u*(uint32_t)((h*Dn + k*16 + (lane & 15))*XHP
                                                      + lh*32 + lp*16 + ((lane >> 4) << 3)));
                mma16816(acc[lp*2+0], a[k], bb);
                mma16816(acc[lp*2+1], a[k], bb + 2);
            }
        }

        const int r1  = lane >> 2;
        const int c2  = (lane & 3)*2;
        const int hq1 = h*Qn + r1, hq2 = hq1 + 8;
        const float S1 = S_s[hq1], T1 = T_s[hq1];
        const float S2 = S_s[hq2], T2 = T_s[hq2];
        #pragma unroll
        for (int j = 0; j < 4; j++) {
            #pragma unroll
            for (int e = 0; e < 2; e++) {
                float2 st = stats_s[lh*32 + j*8 + c2 + e];
                float base = st.y * st.x;
                acc[j][e]   = fmaf(acc[j][e],   st.y, fmaf(-base, S1, T1));
                acc[j][2+e] = fmaf(acc[j][2+e], st.y, fmaf(-base, S2, T2));
            }
        }

        float m1 = -1e30f, m2 = -1e30f;
        #pragma unroll
        for (int j = 0; j < 4; j++) {
            m1 = fmaxf(m1, fmaxf(acc[j][0], acc[j][1]));
            m2 = fmaxf(m2, fmaxf(acc[j][2], acc[j][3]));
        }
        m1 = fmaxf(m1, __shfl_xor_sync(0xFFFFFFFFu, m1, 1));
        m1 = fmaxf(m1, __shfl_xor_sync(0xFFFFFFFFu, m1, 2));
        m2 = fmaxf(m2, __shfl_xor_sync(0xFFFFFFFFu, m2, 1));
        m2 = fmaxf(m2, __shfl_xor_sync(0xFFFFFFFFu, m2, 2));

        float s1 = 0.f, s2 = 0.f;
        #pragma unroll
        for (int j = 0; j < 4; j++) {
            acc[j][0] = fexp(acc[j][0] - m1);
            acc[j][1] = fexp(acc[j][1] - m1);
            acc[j][2] = fexp(acc[j][2] - m2);
            acc[j][3] = fexp(acc[j][3] - m2);
            s1 += acc[j][0] + acc[j][1];
            s2 += acc[j][2] + acc[j][3];
        }
        s1 += __shfl_xor_sync(0xFFFFFFFFu, s1, 1);
        s1 += __shfl_xor_sync(0xFFFFFFFFu, s1, 2);
        s2 += __shfl_xor_sync(0xFFFFFFFFu, s2, 1);
        s2 += __shfl_xor_sync(0xFFFFFFFFu, s2, 2);

        if ((lane & 3) == 0) {
            redms[h][lh][r1]     = make_float2(m1, s1);
            redms[h][lh][r1 + 8] = make_float2(m2, s2);
        }
        __syncthreads();

        float2 o1 = redms[h][1 - lh][r1];
        float2 o2 = redms[h][1 - lh][r1 + 8];
        float mt1 = fmaxf(m1, o1.x), mt2 = fmaxf(m2, o2.x);
        float f1  = fexp(m1 - mt1),  f2  = fexp(m2 - mt2);
        if (lh == 0 && (lane & 3) == 0) {
            float se1 = s1*f1 + o1.y*fexp(o1.x - mt1);
            float se2 = s2*f2 + o2.y*fexp(o2.x - mt2);
            g_part[(b*NT1 + tile)*NHQ + hq1] = make_float2(mt1, se1);
            g_part[(b*NT1 + tile)*NHQ + hq2] = make_float2(mt2, se2);
        }

        __half* e1 = g_E + (size_t)(b*NHQ + hq1)*Ln + tile*LT1 + lh*32;
        __half* e2 = g_E + (size_t)(b*NHQ + hq2)*Ln + tile*LT1 + lh*32;
        #pragma unroll
        for (int j = 0; j < 4; j++) {
            __half2 v1 = __floats2half2_rn(acc[j][0]*f1, acc[j][1]*f1);
            __half2 v2 = __floats2half2_rn(acc[j][2]*f2, acc[j][3]*f2);
            *(__half2*)(e1 + j*8 + c2) = v1;
            *(__half2*)(e2 + j*8 + c2) = v2;
        }
    }
}

// ---------------- K2: merge softmax partials ----------------
__global__ void k2()
{
    const int idx = blockIdx.x*128 + threadIdx.x;
    if (idx >= Bn*NHQ) return;
    const int b = idx >> 7, hq = idx & 127;
    float m = -1e30f;
    for (int t = 0; t < NT1; t++) m = fmaxf(m, g_part[(b*NT1 + t)*NHQ + hq].x);
    float s = 0.f;
    for (int t = 0; t < NT1; t++) {
        float2 p = g_part[(b*NT1 + t)*NHQ + hq];
        s += p.y * fexp(p.x - m);
    }
    g_ms[idx] = make_float2(m, 1.f/s);
}

// ---------------- K3: P = Aw @ xn^T, fp16 GEMM, 3-stage ring (1 barrier/chunk) ----------------
#define A_OFF  0
#define B_OFF  (128*APITCH)
#define TILE_HALVES (128*APITCH + 256*APITCH)   // 27648
#define TILE_BYTES  (TILE_HALVES*2)             // 55296
#define K3_DYN (3*TILE_BYTES)                   // 165888

__global__ __launch_bounds__(512, 1) void k3()
{
    extern __shared__ __half sm3[];
    __shared__ float2 ms_s[NHQ];

    const int split = blockIdx.x, b = blockIdx.y;
    const int tid  = threadIdx.x;
    const int wid  = tid >> 5, lane = tid & 31;
    const int mw   = wid >> 2, nw = wid & 3;

    for (int i = tid; i < NHQ; i += 512) ms_s[i] = g_ms[b*NHQ + i];

    const int hqA = tid >> 2, l0A = (tid & 3) * 16;   // A: 128 rows x 64
    const int cB  = tid >> 1, l0B = (tid & 1) * 32;   // B: 256 rows x 64
    __syncthreads();
    const float m_g = ms_s[hqA].x, inv_s = ms_s[hqA].y;

    const __half* eA = g_E  + (size_t)(b*NHQ + hqA)*Ln + split*LSP + l0A;
    const __half* xB = g_xn + ((size_t)b*Cn + cB)*Ln   + split*LSP + l0B;
    const float2* gp = g_part + (b*NT1 + split*(NT1/NSPLIT))*NHQ + hqA;

    const uint32_t smb = (uint32_t)__cvta_generic_to_shared(sm3);
    const uint32_t dstB = smb + 2u*(uint32_t)(B_OFF + cB*APITCH + l0B);

    const int g = lane >> 3, r = lane & 7;
    const uint32_t addrA0 = smb + 2u*((uint32_t)((mw*32 + ((g & 1) << 3) + r)*APITCH + ((g >> 1) << 3)));
    const uint32_t addrB0 = smb + 2u*((uint32_t)(B_OFF + (nw*64 + ((g >> 1) << 3) + r)*APITCH + ((g & 1) << 3)));

    float acc[2][8][4];
    #pragma unroll
    for (int i = 0; i < 2; i++)
        #pragma unroll
        for (int j = 0; j < 8; j++)
            #pragma unroll
            for (int e = 0; e < 4; e++) acc[i][j][e] = 0.f;

    auto storeA = [&](uint32_t half_off, const uint4* ar, float f) {
        #pragma unroll
        for (int u = 0; u < 2; u++) {
            uint32_t w[4] = {ar[u].x, ar[u].y, ar[u].z, ar[u].w};
            uint32_t o[4];
            #pragma unroll
            for (int j = 0; j < 4; j++) {
                __half2 h = *reinterpret_cast<__half2*>(&w[j]);
                float2 v = __half22float2(h);
                __half2 rr = __floats2half2_rn(v.x * f, v.y * f);
                o[j] = *reinterpret_cast<uint32_t*>(&rr);
            }
            *(uint4*)(sm3 + half_off + A_OFF + hqA*APITCH + l0A + u*8) =
                make_uint4(o[0], o[1], o[2], o[3]);
        }
    };

    // ---- prologue: B(0) via cp.async; A(0) stored; A(1) regs loaded ----
    {
        CP_ASYNC16(dstB +  0, xB);
        CP_ASYNC16(dstB + 16, xB + 8);
        CP_ASYNC16(dstB + 32, xB + 16);
        CP_ASYNC16(dstB + 48, xB + 24);
        CP_COMMIT();
    }
    uint4 aregs[2];
    aregs[0] = *(const uint4*)(eA);
    aregs[1] = *(const uint4*)(eA + 8);
    storeA(0, aregs, fexp(gp[0].x - m_g) * inv_s);
    aregs[0] = *(const uint4*)(eA + KC);
    aregs[1] = *(const uint4*)(eA + KC + 8);
    float fcur = fexp(gp[NHQ].x - m_g) * inv_s;   // factor for chunk 1

    for (int t = 0; t < NCHUNK; t++) {
        const uint32_t bufo = (uint32_t)((t % 3) * TILE_BYTES);

        if (t + 1 < NCHUNK) {
            const uint32_t nb = (uint32_t)(((t + 1) % 3) * TILE_BYTES);
            const __half* src = xB + (t + 1)*KC;
            CP_ASYNC16(nb + dstB +  0, src);
            CP_ASYNC16(nb + dstB + 16, src + 8);
            CP_ASYNC16(nb + dstB + 32, src + 16);
            CP_ASYNC16(nb + dstB + 48, src + 24);
            CP_COMMIT();
            storeA(nb >> 1, aregs, fcur);
            if (t + 2 < NCHUNK) {
                const __half* ea = eA + (t + 2)*KC;
                aregs[0] = *(const uint4*)(ea);
                aregs[1] = *(const uint4*)(ea + 8);
                fcur = fexp(gp[(t + 2)*NHQ].x - m_g) * inv_s;
            }
            CP_WAIT1();
        } else {
            CP_WAIT0();
        }
        __syncthreads();

        // ---- MMA(t) ----
        #pragma unroll
        for (int ks = 0; ks < 4; ks++) {
            uint32_t a0[4], a1[4];
            ldm_x4(a0, bufo + addrA0 + 2u*(uint32_t)(16*ks));
            ldm_x4(a1, bufo + addrA0 + 2u*(uint32_t)(16*APITCH + 16*ks));
            #pragma unroll
            for (int jj = 0; jj < 4; jj++) {
                uint32_t bfr[4];
                ldm_x4(bfr, bufo + addrB0 + 2u*(uint32_t)(16*jj*APITCH + 16*ks));
                mma16816(acc[0][2*jj],   a0, bfr);
                mma16816(acc[0][2*jj+1], a0, bfr + 2);
                mma16816(acc[1][2*jj],   a1, bfr);
                mma16816(acc[1][2*jj+1], a1, bfr + 2);
            }
        }
    }

    // ---- epilogue: write P partial ----
    float* pp = g_Ppart + (((size_t)split*Bn + b)*NHQ)*Cn;
    #pragma unroll
    for (int i = 0; i < 2; i++) {
        const int row = mw*32 + i*16 + (lane >> 2);
        #pragma unroll
        for (int j = 0; j < 8; j++) {
            const int col = nw*64 + j*8 + (lane & 3)*2;
            *(float2*)(pp + (size_t)row*Cn + col)     = make_float2(acc[i][j][0], acc[i][j][1]);
            *(float2*)(pp + (size_t)(row+8)*Cn + col) = make_float2(acc[i][j][2], acc[i][j][3]);
        }
    }
}

// ---------------- K4a: reduce P partials, A = P @ val_w^T (per head) + val_b ----------------
// 2 outputs (q, q+8) per thread sharing the vw row -> fewer LDS per FMA.
__global__ void k4a(const float* __restrict__ val_w, const float* __restrict__ val_b)
{
    extern __shared__ float sm[];
    float* vw = sm;             // [32][VWP]
    float* ps = sm + 32*VWP;    // [16][256]
    const int h = blockIdx.x, b = blockIdx.y;
    const int tid = threadIdx.x;

    for (int i = tid*4; i < 32*Cn; i += 256*4) {
        int r = i >> 8, c = i & 255;
        float4 v = *(const float4*)&val_w[(size_t)(h*32 + r)*Cn + c];
        *(float4*)&vw[r*VWP + c] = v;
    }
    for (int i = tid*4; i < Qn*Cn; i += 256*4) {
        int q = i >> 8, c = i & 255;
        int hq = h*Qn + q;
        float4 s0 = *(const float4*)&g_Ppart[(((size_t)0*Bn + b)*NHQ + hq)*Cn + c];
        float4 s1 = *(const float4*)&g_Ppart[(((size_t)1*Bn + b)*NHQ + hq)*Cn + c];
        *(float4*)&ps[i] = make_float4(s0.x + s1.x, s0.y + s1.y, s0.z + s1.z, s0.w + s1.w);
    }
    __syncthreads();

    {
        const int q = tid >> 5;       // 0..7 (pairs with q+8)
        const int d = tid & 31;
        float a0 = val_b[h*32 + d];
        float a1 = a0;
        const float* psr0 = &ps[q*Cn];
        const float* psr1 = &ps[(q + 8)*Cn];
        const float* wvr  = &vw[d*VWP];
        #pragma unroll 8
        for (int c = 0; c < Cn; c += 4) {
            float4 wv = *(const float4*)&wvr[c];
            float4 p0 = *(const float4*)&psr0[c];
            float4 p1 = *(const float4*)&psr1[c];
            a0 = fmaf(p0.x, wv.x, a0); a1 = fmaf(p1.x, wv.x, a1);
            a0 = fmaf(p0.y, wv.y, a0); a1 = fmaf(p1.y, wv.y, a1);
            a0 = fmaf(p0.z, wv.z, a0); a1 = fmaf(p1.z, wv.z, a1);
            a0 = fmaf(p0.w, wv.w, a0); a1 = fmaf(p1.w, wv.w, a1);
        }
        g_A[b*4096 + (h*Qn + q)*32 + d]       = a0;
        g_A[b*4096 + (h*Qn + q + 8)*32 + d]   = a1;
    }
}

// ---------------- K4b: out = A @ fin_w^T + fin_b ----------------
__global__ void kinit(float* __restrict__ out, const float* __restrict__ fin_b)
{
    out[blockIdx.x*FHn + threadIdx.x] = fin_b[threadIdx.x];
}

__global__ void k4b(const float* __restrict__ fin_w, float* __restrict__ out)
{
    __shared__ float At[64*65];
    __shared__ float Wt[32*65];
    const int ft = blockIdx.x;
    const int js = blockIdx.y;
    const int tid = threadIdx.x;
    const int ty = tid >> 5, tx = tid & 31;
    const int f0 = ft*32;

    float acc[8];
    #pragma unroll
    for (int i = 0; i < 8; i++) acc[i] = 0.f;

    for (int sub = 0; sub < 8; sub++) {
        const int j0 = js*512 + sub*64;
        __syncthreads();
        for (int i = tid; i < 64*64; i += 256) {
            int bb = i >> 6, jj = i & 63;
            At[bb*65 + jj] = g_A[bb*4096 + j0 + jj];
        }
        for (int i = tid; i < 32*64; i += 256) {
            int r = i >> 6, jj = i & 63;
            Wt[r*65 + jj] = fin_w[(size_t)(f0 + r)*4096 + j0 + jj];
        }
        __syncthreads();
        #pragma unroll 8
        for (int j = 0; j < 64; j++) {
            float w = Wt[tx*65 + j];
            #pragma unroll
            for (int i = 0; i < 8; i++)
                acc[i] = fmaf(At[(ty*8 + i)*65 + j], w, acc[i]);
        }
    }
    #pragma unroll
    for (int i = 0; i < 8; i++)
        atomicAdd(&out[(ty*8 + i)*FHn + f0 + tx], acc[i]);
}

// ---------------- launch ----------------
extern "C" void kernel_launch(void* const* d_in, const int* in_sizes, int n_in,
                              void* d_out, int out_size)
{
    const float* x    = (const float*)d_in[0];
    const float* gam  = (const float*)d_in[1];
    const float* bet  = (const float*)d_in[2];
    const float* attw = (const float*)d_in[3];
    const float* valw = (const float*)d_in[4];
    const float* valb = (const float*)d_in[5];
    const float* finw = (const float*)d_in[6];
    const float* finb = (const float*)d_in[7];
    float* out = (float*)d_out;

    const int smem_k4a = (32*VWP + 16*Cn)*4;

    cudaFuncSetAttribute(k1,  cudaFuncAttributeMaxDynamicSharedMemorySize, K1_DYN);
    cudaFuncSetAttribute(k3,  cudaFuncAttributeMaxDynamicSharedMemorySize, K3_DYN);
    cudaFuncSetAttribute(k4a, cudaFuncAttributeMaxDynamicSharedMemorySize, smem_k4a);

    // k3 is the 4th launch -> ncu capture lands on the GEMM
    kinit<<<Bn, FHn>>>(out, finb);
    k1  <<<dim3(NT1, Bn),    512, K1_DYN >>>(x, gam, bet, attw);
    k2  <<<64, 128>>>();
    k3  <<<dim3(NSPLIT, Bn), 512, K3_DYN >>>();
    k4a <<<dim3(HEADSn, Bn), 256, smem_k4a>>>(valw, valb);
    k4b <<<dim3(16, 8), 256>>>(finw, out);
}

// round 17
// speedup vs baseline: 1.2602x; 1.0282x over previous
#include <cuda_runtime.h>
#include <cuda_fp16.h>
#include <cstdint>
#include <math.h>

#define Bn      64
#define Cn      256
#define Ln      4096
#define HEADSn  8
#define Qn      16
#define Dn      32
#define NHQ     128          // HEADS*Q
#define FHn     512
#define LT1     64           // K1 tile (l per block)
#define NT1     64           // number of K1 tiles (Ln/LT1)
#define NSPLIT  2
#define LSP     2048         // L per split (Ln/NSPLIT)
#define KC      64           // K3 l-chunk (== LT1)
#define NCHUNK  (LSP/KC)     // 32
#define APITCH  72           // fp16 elems per row (144B pitch -> ldmatrix conflict-free)
#define VWP     260          // k4a vw pitch (float4 conflict-free)
#define XHP     72           // k1 x_h smem pitch (halves)
#define GP      40           // k1 G smem pitch (halves; 80B stride, conflict-free)

// ---------------- scratch (device globals: no allocs allowed) ----------------
// g_E rows are stored in MMA-fragment order: within each 32-half group,
// half position p = lq*8 + j*2 + e holds the value for l = j*8 + lq*2 + e
// (self-inverse transpose; k3's storeA applies it when writing SMEM).
__device__ __half  g_E  [(size_t)Bn*NHQ*Ln];               // 67 MB  exp(logit - m_tile), fp16
__device__ __half  g_xn [(size_t)Bn*Cn*Ln];                // 134 MB LayerNormed x, fp16
__device__ float2  g_part[Bn*NT1*NHQ];                     // per-tile (max, sumexp)
__device__ float2  g_ms  [Bn*NHQ];                         // (max, 1/sum)
__device__ float   g_Ppart[(size_t)NSPLIT*Bn*NHQ*Cn];      // 17 MB partial P
__device__ float   g_A   [Bn*NHQ*Dn];                      // Aflat [B,4096]

// ---------------- fast exp (no MUFU; pure FMA/ALU) ----------------
__device__ __forceinline__ float fexp(float x) {
    float y = x * 1.4426950408889634f;
    y = fmaxf(y, -120.0f);
    float fl = floorf(y);
    float f  = y - fl;                 // [0,1)
    float p = 1.5252733e-5f;
    p = fmaf(p, f, 1.5403530e-4f);
    p = fmaf(p, f, 1.3333558e-3f);
    p = fmaf(p, f, 9.6181291e-3f);
    p = fmaf(p, f, 5.5504109e-2f);
    p = fmaf(p, f, 2.4022651e-1f);
    p = fmaf(p, f, 6.9314718e-1f);
    p = fmaf(p, f, 1.0f);
    int i = (int)fl;
    return p * __int_as_float((i + 127) << 23);
}

// mma.sync m16n8k16 fp16 (row.col), fp32 accumulate — base-arch tensor path
__device__ __forceinline__ void mma16816(float* d, const uint32_t* a, const uint32_t* b) {
    asm volatile("mma.sync.aligned.m16n8k16.row.col.f32.f16.f16.f32 "
        "{%0,%1,%2,%3}, {%4,%5,%6,%7}, {%8,%9}, {%0,%1,%2,%3};"
        : "+f"(d[0]), "+f"(d[1]), "+f"(d[2]), "+f"(d[3])
        : "r"(a[0]), "r"(a[1]), "r"(a[2]), "r"(a[3]), "r"(b[0]), "r"(b[1]));
}

__device__ __forceinline__ void ldm_x4(uint32_t* r, uint32_t addr) {
    asm volatile("ldmatrix.sync.aligned.m8n8.x4.shared.b16 {%0,%1,%2,%3}, [%4];"
        : "=r"(r[0]), "=r"(r[1]), "=r"(r[2]), "=r"(r[3]) : "r"(addr));
}
__device__ __forceinline__ void ldm_x4_trans(uint32_t* r, uint32_t addr) {
    asm volatile("ldmatrix.sync.aligned.m8n8.x4.trans.shared.b16 {%0,%1,%2,%3}, [%4];"
        : "=r"(r[0]), "=r"(r[1]), "=r"(r[2]), "=r"(r[3]) : "r"(addr));
}

#define CP_ASYNC16(dst, src) \
    asm volatile("cp.async.ca.shared.global [%0], [%1], 16;" :: "r"(dst), "l"(src) : "memory")
#define CP_COMMIT()  asm volatile("cp.async.commit_group;" ::: "memory")
#define CP_WAIT1()   asm volatile("cp.async.wait_group 1;" ::: "memory")
#define CP_WAIT0()   asm volatile("cp.async.wait_group 0;" ::: "memory")

// ---------------- K1: LN stats + tensor-core logits + softmax partials + E/xn ----------------
#define XH_BYTES (Cn*XHP*2)                 // 36864
#define RED_OFF  (XH_BYTES)
#define K1_DYN   (XH_BYTES + 512*16*2)      // 53248

__global__ __launch_bounds__(512, 2) void k1(const float* __restrict__ x,
                                             const float* __restrict__ gamma,
                                             const float* __restrict__ beta,
                                             const float* __restrict__ attw)
{
    extern __shared__ char sm1[];
    __half* x_h  = (__half*)sm1;                  // [256][XHP] halves (raw x fp16)
    float4* redS = (float4*)(sm1 + RED_OFF);      // [512]
    float4* redQ = redS + 512;                    // [512]

    __shared__ __half G_s[NHQ*GP];                // G = w*gamma, [hq][GP]
    __shared__ float  S_s[NHQ], T_s[NHQ];
    __shared__ float2 stats_s[LT1];               // (mu, rstd)
    __shared__ float  gms[Cn], bts[Cn];
    __shared__ float2 redms[HEADSn][2][Qn];       // cross-warp (m,s) exchange

    const int b = blockIdx.y, tile = blockIdx.x;
    const int tid  = threadIdx.x;
    const int lgrp = tid & 15;
    const int l4   = tile*LT1 + lgrp*4;

    for (int i = tid; i < Cn; i += 512) { gms[i] = gamma[i]; bts[i] = beta[i]; }
    __syncthreads();

    // ---- phase 0: G (fp16), S, T per hq ----
    if (tid < NHQ) {
        const int h = tid >> 4;
        const float* wp = attw + tid*Dn;
        float S = 0.f, T = 0.f;
        __half2* grow = (__half2*)&G_s[tid*GP];
        #pragma unroll
        for (int c2 = 0; c2 < 16; c2++) {
            float w0 = wp[2*c2], w1 = wp[2*c2+1];
            float G0 = w0 * gms[h*Dn + 2*c2];
            float G1 = w1 * gms[h*Dn + 2*c2 + 1];
            S += G0 + G1;
            T += w0*bts[h*Dn + 2*c2] + w1*bts[h*Dn + 2*c2 + 1];
            grow[c2] = __floats2half2_rn(G0, G1);
        }
        S_s[tid] = S; T_s[tid] = T;
    }

    const float* xb = x + (size_t)b*Cn*Ln;

    // ---- phase A: stats from fp32 x; stage raw x as fp16 into SMEM ----
    {
        const int cg = tid >> 4;                  // 32 groups of 8 channels
        float4 s4 = make_float4(0.f,0.f,0.f,0.f);
        float4 q4 = make_float4(0.f,0.f,0.f,0.f);
        #pragma unroll
        for (int cc = 0; cc < 8; cc++) {
            const int c = cg*8 + cc;
            float4 v = *(const float4*)&xb[(size_t)c*Ln + l4];
            s4.x += v.x; s4.y += v.y; s4.z += v.z; s4.w += v.w;
            q4.x = fmaf(v.x, v.x, q4.x); q4.y = fmaf(v.y, v.y, q4.y);
            q4.z = fmaf(v.z, v.z, q4.z); q4.w = fmaf(v.w, v.w, q4.w);
            __half2 a01 = __floats2half2_rn(v.x, v.y);
            __half2 a23 = __floats2half2_rn(v.z, v.w);
            *(uint2*)&x_h[c*XHP + lgrp*4] =
                make_uint2(*reinterpret_cast<uint32_t*>(&a01),
                           *reinterpret_cast<uint32_t*>(&a23));
        }
        redS[tid] = s4; redQ[tid] = q4;
        __syncthreads();
        if (tid < LT1) {
            const int lg = tid >> 2, li = tid & 3;
            float s = 0.f, q = 0.f;
            #pragma unroll
            for (int cg2 = 0; cg2 < 32; cg2++) {
                s += ((const float*)&redS[cg2*16 + lg])[li];
                q += ((const float*)&redQ[cg2*16 + lg])[li];
            }
            float mu  = s * (1.f/Cn);
            float var = q * (1.f/Cn) - mu*mu;
            stats_s[tid] = make_float2(mu, rsqrtf(var + 1e-6f));
        }
        __syncthreads();
    }

    // ---- phase B: xn = LN(x) from x_h -> g_xn ----
    {
        const int cg = tid >> 4;
        float2 st0 = stats_s[lgrp*4+0], st1 = stats_s[lgrp*4+1];
        float2 st2 = stats_s[lgrp*4+2], st3 = stats_s[lgrp*4+3];
        __half* xnb = g_xn + (size_t)b*Cn*Ln;
        #pragma unroll
        for (int cc = 0; cc < 8; cc++) {
            const int c = cg*8 + cc;
            uint2 u = *(const uint2*)&x_h[c*XHP + lgrp*4];
            float2 f01 = __half22float2(*reinterpret_cast<__half2*>(&u.x));
            float2 f23 = __half22float2(*reinterpret_cast<__half2*>(&u.y));
            const float gg = gms[c], bb = bts[c];
            __half2 o01 = __floats2half2_rn((f01.x - st0.x)*st0.y*gg + bb,
                                            (f01.y - st1.x)*st1.y*gg + bb);
            __half2 o23 = __floats2half2_rn((f23.x - st2.x)*st2.y*gg + bb,
                                            (f23.y - st3.x)*st3.y*gg + bb);
            *(uint2*)&xnb[(size_t)c*Ln + l4] =
                make_uint2(*reinterpret_cast<uint32_t*>(&o01),
                           *reinterpret_cast<uint32_t*>(&o23));
        }
    }

    // ---- phase C: logits via mma.sync; softmax; E store (fragment-native layout) ----
    {
        const int w    = tid >> 5, lane = tid & 31;
        const int h    = w >> 1, lh = w & 1;       // head, l-half (32 l)
        const int g    = lane >> 3, r = lane & 7;

        const uint32_t smbG = (uint32_t)__cvta_generic_to_shared(G_s);
        const uint32_t smbX = (uint32_t)__cvta_generic_to_shared(x_h);

        uint32_t a[2][4];
        #pragma unroll
        for (int k = 0; k < 2; k++)
            ldm_x4(a[k], smbG + 2u*(uint32_t)((h*16 + ((g & 1) << 3) + r)*GP + k*16 + ((g >> 1) << 3)));

        float acc[4][4];
        #pragma unroll
        for (int j = 0; j < 4; j++)
            #pragma unroll
            for (int e = 0; e < 4; e++) acc[j][e] = 0.f;

        #pragma unroll
        for (int k = 0; k < 2; k++) {
            #pragma unroll
            for (int lp = 0; lp < 2; lp++) {
                uint32_t bb[4];
                ldm_x4_trans(bb, smbX + 2u*(uint32_t)((h*Dn + k*16 + (lane & 15))*XHP
                                                      + lh*32 + lp*16 + ((lane >> 4) << 3)));
                mma16816(acc[lp*2+0], a[k], bb);
                mma16816(acc[lp*2+1], a[k], bb + 2);
            }
        }

        const int r1  = lane >> 2;
        const int c2  = (lane & 3)*2;
        const int hq1 = h*Qn + r1, hq2 = hq1 + 8;
        const float S1 = S_s[hq1], T1 = T_s[hq1];
        const float S2 = S_s[hq2], T2 = T_s[hq2];
        #pragma unroll
        for (int j = 0; j < 4; j++) {
            #pragma unroll
            for (int e = 0; e < 2; e++) {
                float2 st = stats_s[lh*32 + j*8 + c2 + e];
                float base = st.y * st.x;
                acc[j][e]   = fmaf(acc[j][e],   st.y, fmaf(-base, S1, T1));
                acc[j][2+e] = fmaf(acc[j][2+e], st.y, fmaf(-base, S2, T2));
            }
        }

        float m1 = -1e30f, m2 = -1e30f;
        #pragma unroll
        for (int j = 0; j < 4; j++) {
            m1 = fmaxf(m1, fmaxf(acc[j][0], acc[j][1]));
            m2 = fmaxf(m2, fmaxf(acc[j][2], acc[j][3]));
        }
        m1 = fmaxf(m1, __shfl_xor_sync(0xFFFFFFFFu, m1, 1));
        m1 = fmaxf(m1, __shfl_xor_sync(0xFFFFFFFFu, m1, 2));
        m2 = fmaxf(m2, __shfl_xor_sync(0xFFFFFFFFu, m2, 1));
        m2 = fmaxf(m2, __shfl_xor_sync(0xFFFFFFFFu, m2, 2));

        float s1 = 0.f, s2 = 0.f;
        #pragma unroll
        for (int j = 0; j < 4; j++) {
            acc[j][0] = fexp(acc[j][0] - m1);
            acc[j][1] = fexp(acc[j][1] - m1);
            acc[j][2] = fexp(acc[j][2] - m2);
            acc[j][3] = fexp(acc[j][3] - m2);
            s1 += acc[j][0] + acc[j][1];
            s2 += acc[j][2] + acc[j][3];
        }
        s1 += __shfl_xor_sync(0xFFFFFFFFu, s1, 1);
        s1 += __shfl_xor_sync(0xFFFFFFFFu, s1, 2);
        s2 += __shfl_xor_sync(0xFFFFFFFFu, s2, 1);
        s2 += __shfl_xor_sync(0xFFFFFFFFu, s2, 2);

        if ((lane & 3) == 0) {
            redms[h][lh][r1]     = make_float2(m1, s1);
            redms[h][lh][r1 + 8] = make_float2(m2, s2);
        }
        __syncthreads();

        float2 o1 = redms[h][1 - lh][r1];
        float2 o2 = redms[h][1 - lh][r1 + 8];
        float mt1 = fmaxf(m1, o1.x), mt2 = fmaxf(m2, o2.x);
        float f1  = fexp(m1 - mt1),  f2  = fexp(m2 - mt2);
        if (lh == 0 && (lane & 3) == 0) {
            float se1 = s1*f1 + o1.y*fexp(o1.x - mt1);
            float se2 = s2*f2 + o2.y*fexp(o2.x - mt2);
            g_part[(b*NT1 + tile)*NHQ + hq1] = make_float2(mt1, se1);
            g_part[(b*NT1 + tile)*NHQ + hq2] = make_float2(mt2, se2);
        }

        // E stores in fragment-native order: one uint4 (8 halves) per lane per row.
        // half position p = lq*8 + j*2 + e  <->  l = j*8 + lq*2 + e  (k3 inverts).
        const int lq = lane & 3;
        uint32_t pk1[4], pk2[4];
        #pragma unroll
        for (int j = 0; j < 4; j++) {
            __half2 v1 = __floats2half2_rn(acc[j][0]*f1, acc[j][1]*f1);
            __half2 v2 = __floats2half2_rn(acc[j][2]*f2, acc[j][3]*f2);
            pk1[j] = *reinterpret_cast<uint32_t*>(&v1);
            pk2[j] = *reinterpret_cast<uint32_t*>(&v2);
        }
        __half* e1 = g_E + (size_t)(b*NHQ + hq1)*Ln + tile*LT1 + lh*32 + lq*8;
        __half* e2 = g_E + (size_t)(b*NHQ + hq2)*Ln + tile*LT1 + lh*32 + lq*8;
        *(uint4*)e1 = make_uint4(pk1[0], pk1[1], pk1[2], pk1[3]);
        *(uint4*)e2 = make_uint4(pk2[0], pk2[1], pk2[2], pk2[3]);
    }
}

// ---------------- K2: merge softmax partials ----------------
__global__ void k2()
{
    const int idx = blockIdx.x*128 + threadIdx.x;
    if (idx >= Bn*NHQ) return;
    const int b = idx >> 7, hq = idx & 127;
    float m = -1e30f;
    for (int t = 0; t < NT1; t++) m = fmaxf(m, g_part[(b*NT1 + t)*NHQ + hq].x);
    float s = 0.f;
    for (int t = 0; t < NT1; t++) {
        float2 p = g_part[(b*NT1 + t)*NHQ + hq];
        s += p.y * fexp(p.x - m);
    }
    g_ms[idx] = make_float2(m, 1.f/s);
}

// ---------------- K3: P = Aw @ xn^T, fp16 GEMM, 3-stage ring (1 barrier/chunk) ----------------
#define A_OFF  0
#define B_OFF  (128*APITCH)
#define TILE_HALVES (128*APITCH + 256*APITCH)   // 27648
#define TILE_BYTES  (TILE_HALVES*2)             // 55296
#define K3_DYN (3*TILE_BYTES)                   // 165888

__global__ __launch_bounds__(512, 1) void k3()
{
    extern __shared__ __half sm3[];
    __shared__ float2 ms_s[NHQ];

    const int split = blockIdx.x, b = blockIdx.y;
    const int tid  = threadIdx.x;
    const int wid  = tid >> 5, lane = tid & 31;
    const int mw   = wid >> 2, nw = wid & 3;

    for (int i = tid; i < NHQ; i += 512) ms_s[i] = g_ms[b*NHQ + i];

    const int hqA = tid >> 2, l0A = (tid & 3) * 16;   // A: 128 rows x 64 (permuted layout)
    const int cB  = tid >> 1, l0B = (tid & 1) * 32;   // B: 256 rows x 64
    __syncthreads();
    const float m_g = ms_s[hqA].x, inv_s = ms_s[hqA].y;

    const __half* eA = g_E  + (size_t)(b*NHQ + hqA)*Ln + split*LSP + l0A;
    const __half* xB = g_xn + ((size_t)b*Cn + cB)*Ln   + split*LSP + l0B;
    const float2* gp = g_part + (b*NT1 + split*(NT1/NSPLIT))*NHQ + hqA;

    const uint32_t smb = (uint32_t)__cvta_generic_to_shared(sm3);
    const uint32_t dstB = smb + 2u*(uint32_t)(B_OFF + cB*APITCH + l0B);

    const int g = lane >> 3, r = lane & 7;
    const uint32_t addrA0 = smb + 2u*((uint32_t)((mw*32 + ((g & 1) << 3) + r)*APITCH + ((g >> 1) << 3)));
    const uint32_t addrB0 = smb + 2u*((uint32_t)(B_OFF + (nw*64 + ((g >> 1) << 3) + r)*APITCH + ((g & 1) << 3)));

    float acc[2][8][4];
    #pragma unroll
    for (int i = 0; i < 2; i++)
        #pragma unroll
        for (int j = 0; j < 8; j++)
            #pragma unroll
            for (int e = 0; e < 4; e++) acc[i][j][e] = 0.f;

    // convert+store A(chunk): aregs hold PERMUTED g_E halves; write each __half2
    // to its natural-l SMEM slot (inverse transpose), so downstream MMA is unchanged.
    const int q2 = tid & 3;
    const int abase = hqA*APITCH + (q2 >> 1)*32 + (q2 & 1)*4;
    auto storeA = [&](uint32_t half_off, const uint4* ar, float f) {
        #pragma unroll
        for (int u = 0; u < 2; u++) {
            uint32_t w[4] = {ar[u].x, ar[u].y, ar[u].z, ar[u].w};
            #pragma unroll
            for (int j = 0; j < 4; j++) {
                __half2 h = *reinterpret_cast<__half2*>(&w[j]);
                float2 v = __half22float2(h);
                __half2 rr = __floats2half2_rn(v.x * f, v.y * f);
                *(uint32_t*)(sm3 + half_off + A_OFF + abase + j*8 + u*2) =
                    *reinterpret_cast<uint32_t*>(&rr);
            }
        }
    };

    // ---- prologue: B(0) via cp.async; A(0) stored; A(1) regs loaded ----
    {
        CP_ASYNC16(dstB +  0, xB);
        CP_ASYNC16(dstB + 16, xB + 8);
        CP_ASYNC16(dstB + 32, xB + 16);
        CP_ASYNC16(dstB + 48, xB + 24);
        CP_COMMIT();
    }
    uint4 aregs[2];
    aregs[0] = *(const uint4*)(eA);
    aregs[1] = *(const uint4*)(eA + 8);
    storeA(0, aregs, fexp(gp[0].x - m_g) * inv_s);
    aregs[0] = *(const uint4*)(eA + KC);
    aregs[1] = *(const uint4*)(eA + KC + 8);
    float fcur = fexp(gp[NHQ].x - m_g) * inv_s;   // factor for chunk 1

    for (int t = 0; t < NCHUNK; t++) {
        const uint32_t bufo = (uint32_t)((t % 3) * TILE_BYTES);

        if (t + 1 < NCHUNK) {
            const uint32_t nb = (uint32_t)(((t + 1) % 3) * TILE_BYTES);
            const __half* src = xB + (t + 1)*KC;
            CP_ASYNC16(nb + dstB +  0, src);
            CP_ASYNC16(nb + dstB + 16, src + 8);
            CP_ASYNC16(nb + dstB + 32, src + 16);
            CP_ASYNC16(nb + dstB + 48, src + 24);
            CP_COMMIT();
            storeA(nb >> 1, aregs, fcur);
            if (t + 2 < NCHUNK) {
                const __half* ea = eA + (t + 2)*KC;
                aregs[0] = *(const uint4*)(ea);
                aregs[1] = *(const uint4*)(ea + 8);
                fcur = fexp(gp[(t + 2)*NHQ].x - m_g) * inv_s;
            }
            CP_WAIT1();
        } else {
            CP_WAIT0();
        }
        __syncthreads();

        // ---- MMA(t) ----
        #pragma unroll
        for (int ks = 0; ks < 4; ks++) {
            uint32_t a0[4], a1[4];
            ldm_x4(a0, bufo + addrA0 + 2u*(uint32_t)(16*ks));
            ldm_x4(a1, bufo + addrA0 + 2u*(uint32_t)(16*APITCH + 16*ks));
            #pragma unroll
            for (int jj = 0; jj < 4; jj++) {
                uint32_t bfr[4];
                ldm_x4(bfr, bufo + addrB0 + 2u*(uint32_t)(16*jj*APITCH + 16*ks));
                mma16816(acc[0][2*jj],   a0, bfr);
                mma16816(acc[0][2*jj+1], a0, bfr + 2);
                mma16816(acc[1][2*jj],   a1, bfr);
                mma16816(acc[1][2*jj+1], a1, bfr + 2);
            }
        }
    }

    // ---- epilogue: write P partial ----
    float* pp = g_Ppart + (((size_t)split*Bn + b)*NHQ)*Cn;
    #pragma unroll
    for (int i = 0; i < 2; i++) {
        const int row = mw*32 + i*16 + (lane >> 2);
        #pragma unroll
        for (int j = 0; j < 8; j++) {
            const int col = nw*64 + j*8 + (lane & 3)*2;
            *(float2*)(pp + (size_t)row*Cn + col)     = make_float2(acc[i][j][0], acc[i][j][1]);
            *(float2*)(pp + (size_t)(row+8)*Cn + col) = make_float2(acc[i][j][2], acc[i][j][3]);
        }
    }
}

// ---------------- K4a: reduce P partials, A = P @ val_w^T (per head) + val_b ----------------
__global__ void k4a(const float* __restrict__ val_w, const float* __restrict__ val_b)
{
    extern __shared__ float sm[];
    float* vw = sm;             // [32][VWP]
    float* ps = sm + 32*VWP;    // [16][256]
    const int h = blockIdx.x, b = blockIdx.y;
    const int tid = threadIdx.x;

    for (int i = tid*4; i < 32*Cn; i += 256*4) {
        int r = i >> 8, c = i & 255;
        float4 v = *(const float4*)&val_w[(size_t)(h*32 + r)*Cn + c];
        *(float4*)&vw[r*VWP + c] = v;
    }
    for (int i = tid*4; i < Qn*Cn; i += 256*4) {
        int q = i >> 8, c = i & 255;
        int hq = h*Qn + q;
        float4 s0 = *(const float4*)&g_Ppart[(((size_t)0*Bn + b)*NHQ + hq)*Cn + c];
        float4 s1 = *(const float4*)&g_Ppart[(((size_t)1*Bn + b)*NHQ + hq)*Cn + c];
        *(float4*)&ps[i] = make_float4(s0.x + s1.x, s0.y + s1.y, s0.z + s1.z, s0.w + s1.w);
    }
    __syncthreads();

    {
        const int q = tid >> 5;       // 0..7 (pairs with q+8)
        const int d = tid & 31;
        float a0 = val_b[h*32 + d];
        float a1 = a0;
        const float* psr0 = &ps[q*Cn];
        const float* psr1 = &ps[(q + 8)*Cn];
        const float* wvr  = &vw[d*VWP];
        #pragma unroll 8
        for (int c = 0; c < Cn; c += 4) {
            float4 wv = *(const float4*)&wvr[c];
            float4 p0 = *(const float4*)&psr0[c];
            float4 p1 = *(const float4*)&psr1[c];
            a0 = fmaf(p0.x, wv.x, a0); a1 = fmaf(p1.x, wv.x, a1);
            a0 = fmaf(p0.y, wv.y, a0); a1 = fmaf(p1.y, wv.y, a1);
            a0 = fmaf(p0.z, wv.z, a0); a1 = fmaf(p1.z, wv.z, a1);
            a0 = fmaf(p0.w, wv.w, a0); a1 = fmaf(p1.w, wv.w, a1);
        }
        g_A[b*4096 + (h*Qn + q)*32 + d]       = a0;
        g_A[b*4096 + (h*Qn + q + 8)*32 + d]   = a1;
    }
}

// ---------------- K4b: out = A @ fin_w^T + fin_b ----------------
__global__ void kinit(float* __restrict__ out, const float* __restrict__ fin_b)
{
    out[blockIdx.x*FHn + threadIdx.x] = fin_b[threadIdx.x];
}

__global__ void k4b(const float* __restrict__ fin_w, float* __restrict__ out)
{
    __shared__ float At[64*65];
    __shared__ float Wt[32*65];
    const int ft = blockIdx.x;
    const int js = blockIdx.y;
    const int tid = threadIdx.x;
    const int ty = tid >> 5, tx = tid & 31;
    const int f0 = ft*32;

    float acc[8];
    #pragma unroll
    for (int i = 0; i < 8; i++) acc[i] = 0.f;

    for (int sub = 0; sub < 8; sub++) {
        const int j0 = js*512 + sub*64;
        __syncthreads();
        for (int i = tid; i < 64*64; i += 256) {
            int bb = i >> 6, jj = i & 63;
            At[bb*65 + jj] = g_A[bb*4096 + j0 + jj];
        }
        for (int i = tid; i < 32*64; i += 256) {
            int r = i >> 6, jj = i & 63;
            Wt[r*65 + jj] = fin_w[(size_t)(f0 + r)*4096 + j0 + jj];
        }
        __syncthreads();
        #pragma unroll 8
        for (int j = 0; j < 64; j++) {
            float w = Wt[tx*65 + j];
            #pragma unroll
            for (int i = 0; i < 8; i++)
                acc[i] = fmaf(At[(ty*8 + i)*65 + j], w, acc[i]);
        }
    }
    #pragma unroll
    for (int i = 0; i < 8; i++)
        atomicAdd(&out[(ty*8 + i)*FHn + f0 + tx], acc[i]);
}

// ---------------- launch ----------------
extern "C" void kernel_launch(void* const* d_in, const int* in_sizes, int n_in,
                              void* d_out, int out_size)
{
    const float* x    = (const float*)d_in[0];
    const float* gam  = (const float*)d_in[1];
    const float* bet  = (const float*)d_in[2];
    const float* attw = (const float*)d_in[3];
    const float* valw = (const float*)d_in[4];
    const float* valb = (const float*)d_in[5];
    const float* finw = (const float*)d_in[6];
    const float* finb = (const float*)d_in[7];
    float* out = (float*)d_out;

    const int smem_k4a = (32*VWP + 16*Cn)*4;

    cudaFuncSetAttribute(k1,  cudaFuncAttributeMaxDynamicSharedMemorySize, K1_DYN);
    cudaFuncSetAttribute(k3,  cudaFuncAttributeMaxDynamicSharedMemorySize, K3_DYN);
    cudaFuncSetAttribute(k4a, cudaFuncAttributeMaxDynamicSharedMemorySize, smem_k4a);

    // k3 is the 4th launch -> ncu capture lands on the GEMM
    kinit<<<Bn, FHn>>>(out, finb);
    k1  <<<dim3(NT1, Bn),    512, K1_DYN >>>(x, gam, bet, attw);
    k2  <<<64, 128>>>();
    k3  <<<dim3(NSPLIT, Bn), 512, K3_DYN >>>();
    k4a <<<dim3(HEADSn, Bn), 256, smem_k4a>>>(valw, valb);
    k4b <<<dim3(16, 8), 256>>>(finw, out);
}